// round 9
// baseline (speedup 1.0000x reference)
#include <cuda_runtime.h>
#include <cuda_fp16.h>
#include <stdint.h>

#define TT       365
#define NTHREADS 512
#define MTILE    32
#define NCTA     128
#define KSTEPS   18
#define NTILES   128
#define LDA      296
#define OLD      264   // output scratch stride (floats)

#define SMEM_A_BYTES  (MTILE * LDA * 2)
#define SMEM_O_BYTES  (MTILE * OLD * 4)
#define SMEM_BYTES    (SMEM_A_BYTES + SMEM_O_BYTES)

// fragment-order weights; ntile = warp*8+nt, nt -> gate=nt>>1, sub=nt&1
// n-col = gate*256 + warp*16 + sub*8 + (lane>>2)
__device__ uint2 g_WcSwz[KSTEPS * NTILES * 32];

__global__ void lstm_prep_kernel(const float* __restrict__ w_ih,
                                 const float* __restrict__ w_hh) {
    int g = blockIdx.x * blockDim.x + threadIdx.x;
    if (g >= KSTEPS * NTILES * 32) return;
    int lane = g & 31, ntile = (g >> 5) & 127, ks = g >> 12;
    int warp = ntile >> 3, nt = ntile & 7;
    int n0 = (nt >> 1) * 256 + warp * 16 + (nt & 1) * 8 + (lane >> 2);
    int kb = ks * 16 + 2 * (lane & 3);
    float v[4];
    int ko[4] = {kb, kb + 1, kb + 8, kb + 9};
#pragma unroll
    for (int u = 0; u < 4; u++) {
        int k = ko[u];
        v[u] = (k < 256) ? w_hh[n0 * 256 + k] : w_ih[n0 * 32 + (k - 256)];
    }
    uint2 val;
    val.x = ((unsigned)__half_as_ushort(__float2half(v[1])) << 16)
          |  (unsigned)__half_as_ushort(__float2half(v[0]));
    val.y = ((unsigned)__half_as_ushort(__float2half(v[3])) << 16)
          |  (unsigned)__half_as_ushort(__float2half(v[2]));
    g_WcSwz[g] = val;
}

__device__ __forceinline__ unsigned smem_u32(const void* p) {
    return (unsigned)__cvta_generic_to_shared(p);
}
__device__ __forceinline__ void ldmatrix_x4(unsigned a, unsigned& r0, unsigned& r1,
                                            unsigned& r2, unsigned& r3) {
    asm volatile("ldmatrix.sync.aligned.m8n8.x4.shared.b16 {%0,%1,%2,%3}, [%4];\n"
                 : "=r"(r0), "=r"(r1), "=r"(r2), "=r"(r3) : "r"(a));
}
__device__ __forceinline__ void mma16816(float* c, unsigned a0, unsigned a1,
                                         unsigned a2, unsigned a3,
                                         unsigned b0, unsigned b1) {
    asm volatile(
        "mma.sync.aligned.m16n8k16.row.col.f32.f16.f16.f32 "
        "{%0,%1,%2,%3}, {%4,%5,%6,%7}, {%8,%9}, {%0,%1,%2,%3};\n"
        : "+f"(c[0]), "+f"(c[1]), "+f"(c[2]), "+f"(c[3])
        : "r"(a0), "r"(a1), "r"(a2), "r"(a3), "r"(b0), "r"(b1));
}

// 8-MUFU cell, all-register
__device__ __forceinline__ __half cell(float pi, float pf, float pg, float po,
                                       float& c) {
    float ei = __expf(-pi), ef = __expf(-pf), eo = __expf(-po);
    float eg = __expf(-2.f * fabsf(pg));
    float fg  = __fdividef(1.f, 1.f + ef);
    float itg = (1.f - eg) * __fdividef(1.f, (1.f + ei) * (1.f + eg));
    c = fg * c + copysignf(itg, pg);
    float ec = __expf(-2.f * fabsf(c));
    float hm = (1.f - ec) * __fdividef(1.f, (1.f + eo) * (1.f + ec));
    return __float2half(copysignf(hm, c));
}

__global__ void __launch_bounds__(NTHREADS, 1)
lstm_main_kernel(const float* __restrict__ xd,
                 const float* __restrict__ b,
                 const float* __restrict__ w_out,
                 const float* __restrict__ b_out,
                 float* __restrict__ out) {
    extern __shared__ char smem[];
    __half* A_h  = (__half*)smem;                   // [32][LDA] = [h|x]
    float*  osc  = (float*)(smem + SMEM_A_BYTES);   // [32][OLD] output scratch

    const int tid  = threadIdx.x;
    const int lane = tid & 31;
    const int warp = tid >> 5;
    const int rowbase = blockIdx.x * MTILE;

    const int lrow = lane & 7, lsel = lane >> 3;
    const int aRowOff = lrow + ((lsel & 1) << 3);
    const int aColOff = (lsel >> 1) << 3;
    const int cRow = lane >> 2;
    const int cCol = (lane & 3) * 2;
    const int ubase = warp * 16;                    // warp's unit block

    // this thread's 4 units: ubase + su*8 + cCol + cc
    float bia[4][4];                                // [gate][unit-combo]
#pragma unroll
    for (int su = 0; su < 2; su++)
#pragma unroll
        for (int cc = 0; cc < 2; cc++) {
            int u = ubase + su * 8 + cCol + cc;
#pragma unroll
            for (int gg = 0; gg < 4; gg++) bia[gg][su * 2 + cc] = b[gg * 256 + u];
        }

    float c_reg[16];
#pragma unroll
    for (int k = 0; k < 16; k++) c_reg[k] = 0.f;

    for (int idx = tid; idx < MTILE * 128; idx += NTHREADS) {
        int r = idx >> 7, c2 = idx & 127;
        ((__half2*)(A_h + r * LDA))[c2] = __half2half2(__float2half(0.f));
    }
    {   // stage x_0
        int row = tid >> 4, i2 = tid & 15;
        float2 v = __ldcs((const float2*)(xd + (rowbase + row) * (TT * 32)) + i2);
        ((__half2*)(A_h + row * LDA + 256))[i2] = __floats2half2_rn(v.x, v.y);
    }
    __syncthreads();

    for (int t = 0; t < TT; t++) {
        float acc[2][8][4];
#pragma unroll
        for (int mt = 0; mt < 2; mt++)
#pragma unroll
            for (int nt = 0; nt < 8; nt++)
#pragma unroll
                for (int u = 0; u < 4; u++) acc[mt][nt][u] = 0.f;

#pragma unroll
        for (int ks = 0; ks < KSTEPS; ks++) {
            unsigned a[2][4];
#pragma unroll
            for (int mt = 0; mt < 2; mt++) {
                const __half* p = A_h + (mt * 16 + aRowOff) * LDA + ks * 16 + aColOff;
                ldmatrix_x4(smem_u32(p), a[mt][0], a[mt][1], a[mt][2], a[mt][3]);
            }
            const uint2* wp = g_WcSwz + (ks * NTILES + warp * 8) * 32 + lane;
#pragma unroll
            for (int nt = 0; nt < 8; nt++) {
                uint2 bb = __ldcg(wp + nt * 32);
                mma16816(acc[0][nt], a[0][0], a[0][1], a[0][2], a[0][3], bb.x, bb.y);
                mma16816(acc[1][nt], a[1][0], a[1][1], a[1][2], a[1][3], bb.x, bb.y);
            }
        }

        // prefetch x_{t+1}
        float2 xv;
        const int xrow = tid >> 4, xi2 = tid & 15;
        if (t + 1 < TT)
            xv = __ldcs((const float2*)(xd + (rowbase + xrow) * (TT * 32)
                                        + (t + 1) * 32) + xi2);

        // cells in registers: idx = ((mt*2+rr)*2+su)*2+cc
        __half hres[16];
#pragma unroll
        for (int mt = 0; mt < 2; mt++)
#pragma unroll
            for (int rr = 0; rr < 2; rr++)
#pragma unroll
                for (int su = 0; su < 2; su++)
#pragma unroll
                    for (int cc = 0; cc < 2; cc++) {
                        int ci = ((mt * 2 + rr) * 2 + su) * 2 + cc;
                        int fu = rr * 2 + cc, bu = su * 2 + cc;
                        hres[ci] = cell(acc[mt][su][fu]     + bia[0][bu],
                                        acc[mt][2 + su][fu] + bia[1][bu],
                                        acc[mt][4 + su][fu] + bia[2][bu],
                                        acc[mt][6 + su][fu] + bia[3][bu],
                                        c_reg[ci]);
                    }
        __syncthreads();   // all warps done reading A

#pragma unroll
        for (int mt = 0; mt < 2; mt++)
#pragma unroll
            for (int rr = 0; rr < 2; rr++)
#pragma unroll
                for (int su = 0; su < 2; su++)
#pragma unroll
                    for (int cc = 0; cc < 2; cc++) {
                        int ci = ((mt * 2 + rr) * 2 + su) * 2 + cc;
                        int row = mt * 16 + cRow + rr * 8;
                        int u   = ubase + su * 8 + cCol + cc;
                        A_h[row * LDA + u] = hres[ci];
                    }
        if (t + 1 < TT)
            ((__half2*)(A_h + xrow * LDA + 256))[xi2] = __floats2half2_rn(xv.x, xv.y);
        __syncthreads();
    }

    // output: out[row] = relu(h . w_out + b_out)
    {
        int jj = tid & 255, rh = tid >> 8;
        float wj = w_out[jj];
#pragma unroll
        for (int k = 0; k < 16; k++) {
            int row = rh * 16 + k;
            osc[row * OLD + jj] = __half2float(A_h[row * LDA + jj]) * wj;
        }
    }
    __syncthreads();
    if (tid < 256) {
        float bo0 = b_out[0];
#pragma unroll
        for (int rr = 0; rr < 4; rr++) {
            int k = (tid >> 5) * 4 + rr;
            float s = 0.f;
#pragma unroll
            for (int u = 0; u < 8; u++) s += osc[k * OLD + lane + u * 32];
#pragma unroll
            for (int off = 16; off; off >>= 1) s += __shfl_xor_sync(0xffffffffu, s, off);
            if (lane == 0) out[rowbase + k] = fmaxf(s + bo0, 0.f);
        }
    }
}

extern "C" void kernel_launch(void* const* d_in, const int* in_sizes, int n_in,
                              void* d_out, int out_size) {
    const float* xd    = (const float*)d_in[0];
    const float* w_ih  = (const float*)d_in[1];
    const float* w_hh  = (const float*)d_in[2];
    const float* b     = (const float*)d_in[3];
    const float* w_out = (const float*)d_in[4];
    const float* b_out = (const float*)d_in[5];

    cudaFuncSetAttribute(lstm_main_kernel,
                         cudaFuncAttributeMaxDynamicSharedMemorySize, SMEM_BYTES);
    lstm_prep_kernel<<<288, 256>>>(w_ih, w_hh);
    lstm_main_kernel<<<NCTA, NTHREADS, SMEM_BYTES>>>(xd, b, w_out, b_out,
                                                     (float*)d_out);
}

// round 12
// speedup vs baseline: 1.6851x; 1.6851x over previous
#include <cuda_runtime.h>
#include <cuda_fp16.h>
#include <stdint.h>

#define TT       365
#define NTHREADS 512
#define MTILE    32
#define NCTA     128
#define KSTEPS   18
#define NTILES   128
#define LDA      296
#define GLD4     1028     // gates stride in floats (row = 256 float4 + 1 pad)

#define SMEM_A_BYTES  (MTILE * LDA * 2)            // 18944
#define SMEM_G_BYTES  (MTILE * GLD4 * 4)           // 131584
#define SMEM_BYTES    (SMEM_A_BYTES + SMEM_G_BYTES)

// fragment-order weights, unit-collocated: ntile = warp*8 + nt, nt = gate*2+su
// n-col = gate*256 + warp*16 + su*8 + (lane>>2)   (mapping verified in R9: passed)
__device__ uint2 g_WcSwz[KSTEPS * NTILES * 32];

__global__ void lstm_prep_kernel(const float* __restrict__ w_ih,
                                 const float* __restrict__ w_hh) {
    int g = blockIdx.x * blockDim.x + threadIdx.x;
    if (g >= KSTEPS * NTILES * 32) return;
    int lane = g & 31, ntile = (g >> 5) & 127, ks = g >> 12;
    int warp = ntile >> 3, nt = ntile & 7;
    int n0 = (nt >> 1) * 256 + warp * 16 + (nt & 1) * 8 + (lane >> 2);
    int kb = ks * 16 + 2 * (lane & 3);
    float v[4];
    int ko[4] = {kb, kb + 1, kb + 8, kb + 9};
#pragma unroll
    for (int u = 0; u < 4; u++) {
        int k = ko[u];
        v[u] = (k < 256) ? w_hh[n0 * 256 + k] : w_ih[n0 * 32 + (k - 256)];
    }
    uint2 val;
    val.x = ((unsigned)__half_as_ushort(__float2half(v[1])) << 16)
          |  (unsigned)__half_as_ushort(__float2half(v[0]));
    val.y = ((unsigned)__half_as_ushort(__float2half(v[3])) << 16)
          |  (unsigned)__half_as_ushort(__float2half(v[2]));
    g_WcSwz[g] = val;
}

__device__ __forceinline__ unsigned smem_u32(const void* p) {
    return (unsigned)__cvta_generic_to_shared(p);
}
__device__ __forceinline__ void ldmatrix_x4(unsigned a, unsigned& r0, unsigned& r1,
                                            unsigned& r2, unsigned& r3) {
    asm volatile("ldmatrix.sync.aligned.m8n8.x4.shared.b16 {%0,%1,%2,%3}, [%4];\n"
                 : "=r"(r0), "=r"(r1), "=r"(r2), "=r"(r3) : "r"(a));
}
__device__ __forceinline__ void mma16816(float* c, unsigned a0, unsigned a1,
                                         unsigned a2, unsigned a3,
                                         unsigned b0, unsigned b1) {
    asm volatile(
        "mma.sync.aligned.m16n8k16.row.col.f32.f16.f16.f32 "
        "{%0,%1,%2,%3}, {%4,%5,%6,%7}, {%8,%9}, {%0,%1,%2,%3};\n"
        : "+f"(c[0]), "+f"(c[1]), "+f"(c[2]), "+f"(c[3])
        : "r"(a0), "r"(a1), "r"(a2), "r"(a3), "r"(b0), "r"(b1));
}
__device__ __forceinline__ float tanha(float x) {
    float r; asm("tanh.approx.f32 %0, %1;" : "=f"(r) : "f"(x)); return r;
}

// 5-MUFU cell via tanh.approx
__device__ __forceinline__ __half cell(float pi, float pf, float pg, float po,
                                       float& c) {
    float ig = 0.5f * tanha(0.5f * pi) + 0.5f;
    float fg = 0.5f * tanha(0.5f * pf) + 0.5f;
    float og = 0.5f * tanha(0.5f * po) + 0.5f;
    float gg = tanha(pg);
    c = fg * c + ig * gg;
    return __float2half(og * tanha(c));
}

__global__ void __launch_bounds__(NTHREADS, 1)
lstm_main_kernel(const float* __restrict__ xd,
                 const float* __restrict__ b,
                 const float* __restrict__ w_out,
                 const float* __restrict__ b_out,
                 float* __restrict__ out) {
    extern __shared__ char smem[];
    __half* A_h   = (__half*)smem;                  // [32][LDA] = [h|x]
    float*  gates = (float*)(smem + SMEM_A_BYTES);  // [32][GLD4]: [unit][4 gates]

    const int tid  = threadIdx.x;
    const int lane = tid & 31;
    const int warp = tid >> 5;
    const int rowbase = blockIdx.x * MTILE;

    const int lrow = lane & 7, lsel = lane >> 3;
    const int aRowOff = lrow + ((lsel & 1) << 3);
    const int aColOff = (lsel >> 1) << 3;
    const int cRow = lane >> 2;
    const int cCol = (lane & 3) * 2;
    const int ubase = warp * 16;

    // cell ownership: unit jj, row-half rh
    const int jj = tid & 255;
    const int rh = tid >> 8;
    const float bi = b[jj], bf = b[256 + jj], bg = b[512 + jj], bo = b[768 + jj];

    float c_reg[16];
#pragma unroll
    for (int k = 0; k < 16; k++) c_reg[k] = 0.f;

    for (int idx = tid; idx < MTILE * 128; idx += NTHREADS) {
        int r = idx >> 7, c2 = idx & 127;
        ((__half2*)(A_h + r * LDA))[c2] = __half2half2(__float2half(0.f));
    }
    {   // stage x_0
        int row = tid >> 4, i2 = tid & 15;
        float2 v = __ldcs((const float2*)(xd + (rowbase + row) * (TT * 32)) + i2);
        ((__half2*)(A_h + row * LDA + 256))[i2] = __floats2half2_rn(v.x, v.y);
    }
    __syncthreads();

    for (int t = 0; t < TT; t++) {
        // ---- GEMM: warp computes M=32 x 64 cols (units ubase..+15, 4 gates) ----
        float acc[2][8][4];
#pragma unroll
        for (int mt = 0; mt < 2; mt++)
#pragma unroll
            for (int nt = 0; nt < 8; nt++)
#pragma unroll
                for (int u = 0; u < 4; u++) acc[mt][nt][u] = 0.f;

#pragma unroll
        for (int ks = 0; ks < KSTEPS; ks++) {
            unsigned a[2][4];
#pragma unroll
            for (int mt = 0; mt < 2; mt++) {
                const __half* p = A_h + (mt * 16 + aRowOff) * LDA + ks * 16 + aColOff;
                ldmatrix_x4(smem_u32(p), a[mt][0], a[mt][1], a[mt][2], a[mt][3]);
            }
            const uint2* wp = g_WcSwz + (ks * NTILES + warp * 8) * 32 + lane;
#pragma unroll
            for (int nt = 0; nt < 8; nt++) {
                uint2 bb = __ldcg(wp + nt * 32);
                mma16816(acc[0][nt], a[0][0], a[0][1], a[0][2], a[0][3], bb.x, bb.y);
                mma16816(acc[1][nt], a[1][0], a[1][1], a[1][2], a[1][3], bb.x, bb.y);
            }
        }

        // ---- writeback: gate-interleaved float4 {i,f,g,o} at gates[row][unit] ----
#pragma unroll
        for (int mt = 0; mt < 2; mt++)
#pragma unroll
            for (int rr = 0; rr < 2; rr++)
#pragma unroll
                for (int su = 0; su < 2; su++)
#pragma unroll
                    for (int cc = 0; cc < 2; cc++) {
                        int row = mt * 16 + cRow + rr * 8;
                        int u   = ubase + su * 8 + cCol + cc;
                        int fu  = rr * 2 + cc;
                        *(float4*)&gates[row * GLD4 + u * 4] =
                            make_float4(acc[mt][0 + su][fu], acc[mt][2 + su][fu],
                                        acc[mt][4 + su][fu], acc[mt][6 + su][fu]);
                    }
        __syncthreads();

        // ---- cells: thread owns unit jj, rows rh*16..+15 ----
#pragma unroll
        for (int k = 0; k < 16; k++) {
            int row = rh * 16 + k;
            float4 g4 = *(const float4*)&gates[row * GLD4 + jj * 4];
            A_h[row * LDA + jj] =
                cell(g4.x + bi, g4.y + bf, g4.z + bg, g4.w + bo, c_reg[k]);
        }
        if (t + 1 < TT) {   // stage x_{t+1}
            int row = tid >> 4, i2 = tid & 15;
            float2 v = __ldcs((const float2*)(xd + (rowbase + row) * (TT * 32)
                                              + (t + 1) * 32) + i2);
            ((__half2*)(A_h + row * LDA + 256))[i2] = __floats2half2_rn(v.x, v.y);
        }
        __syncthreads();
    }

    // ---- output: out[row] = relu(h . w_out + b_out); reuse gates as scratch ----
    {
        float wj = w_out[jj];
#pragma unroll
        for (int k = 0; k < 16; k++) {
            int row = rh * 16 + k;
            gates[row * GLD4 + jj] = __half2float(A_h[row * LDA + jj]) * wj;
        }
    }
    __syncthreads();
    if (tid < 256) {
        float bo0 = b_out[0];
#pragma unroll
        for (int rr = 0; rr < 4; rr++) {
            int k = (tid >> 5) * 4 + rr;
            float s = 0.f;
#pragma unroll
            for (int u = 0; u < 8; u++) s += gates[k * GLD4 + lane + u * 32];
#pragma unroll
            for (int off = 16; off; off >>= 1) s += __shfl_xor_sync(0xffffffffu, s, off);
            if (lane == 0) out[rowbase + k] = fmaxf(s + bo0, 0.f);
        }
    }
}

extern "C" void kernel_launch(void* const* d_in, const int* in_sizes, int n_in,
                              void* d_out, int out_size) {
    const float* xd    = (const float*)d_in[0];
    const float* w_ih  = (const float*)d_in[1];
    const float* w_hh  = (const float*)d_in[2];
    const float* b     = (const float*)d_in[3];
    const float* w_out = (const float*)d_in[4];
    const float* b_out = (const float*)d_in[5];

    cudaFuncSetAttribute(lstm_main_kernel,
                         cudaFuncAttributeMaxDynamicSharedMemorySize, SMEM_BYTES);
    lstm_prep_kernel<<<288, 256>>>(w_ih, w_hh);
    lstm_main_kernel<<<NCTA, NTHREADS, SMEM_BYTES>>>(xd, b, w_out, b_out,
                                                     (float*)d_out);
}